// round 15
// baseline (speedup 1.0000x reference)
#include <cuda_runtime.h>
#include <cuda_fp16.h>

#define UU 100000
#define II 50000
#define DD 64
#define EE 2000000
#define NN 150000           // UU + II
#define E2 4000000          // 2*EE
#define NB1 147             // ceil(NN/1024)

#define NB_ITEM 296
#define NB_DEG  7813        // ceil(EE/256)
#define NB_USER 12500       // 100000 warps / 8 per block
#define NB_MAIN (NB_ITEM + NB_DEG + NB_USER)

// ---- static scratch (allocation-free rule) ----
__device__ __half2 g_xh0[NN * 32];   // x0 (half; also the x0 term in the final sum)
__device__ __half2 g_xh1[NN * 32];   // x1
__device__ __half2 g_xh2[NN * 32];   // x2
__device__ float g_dinv[NN];
__device__ unsigned long long g_dc[NN];  // packed: deg fixed<40> | cnt<<40
__device__ int   g_rank[EE];       // per-edge (rank_u | rank_i<<16)
__device__ int   g_incl[NN];       // scan temp (inclusive in-block prefix)
__device__ int   g_ptr[NN + 1];    // CSR offsets
__device__ int2  g_pd[NN];         // (exclusive ptr, bitcast dinv) for k_fill
__device__ int   g_bsum[NB1];      // per-scan1-block totals
__device__ int2  g_csr[E2];        // (src_node, bitcast(norm_weight))

#define DEG_MASK ((1ull << 40) - 1ull)
#define FIX_SCALE 16777216.0f        // 2^24
#define FIX_INV   5.9604644775390625e-8f

// =============== tiny init: packed deg/cnt (self-loop w=1, cnt=0) ===============
__global__ void k_init() {
    int i = blockIdx.x * blockDim.x + threadIdx.x;   // pairs
    if (i * 2 < NN) {
        unsigned long long v = (unsigned long long)(1u << 24);
        ulonglong2* p = (ulonglong2*)g_dc;
        if (i * 2 + 1 < NN) p[i] = make_ulonglong2(v, v);
        else g_dc[i * 2] = v;
    }
}

// =============== fused main: item proj | degree atomics | user norm ===============
__global__ void k_main(const float* __restrict__ user_w,
                       const float* __restrict__ audio,
                       const float* __restrict__ artist_w,
                       const float* __restrict__ album_w,
                       const float* __restrict__ projW,
                       const float* __restrict__ projb,
                       const int* __restrict__ artist_ids,
                       const int* __restrict__ album_ids,
                       const float* __restrict__ ew,
                       const int* __restrict__ u_idx,
                       const int* __restrict__ i_idx) {
    __shared__ float Wt[128 * 64];   // 32 KB only: feat lives in registers
    int b = blockIdx.x;
    int tid = threadIdx.x;
    int wid = tid >> 5, lane = tid & 31;

    if (b < NB_ITEM) {
        // ---- item embeddings: feat in registers, shfl-broadcast GEMV ----
        for (int idx = tid; idx < 64 * 128; idx += 256) {
            int d = idx >> 7, k = idx & 127;
            Wt[k * 64 + d] = projW[idx];
        }
        __syncthreads();
        float2 bb = ((const float2*)projb)[lane];
        int gw = b * 8 + wid;
        int nw = NB_ITEM * 8;
        for (int g = gw; g < II / 4; g += nw) {
            int base = g * 4;
            float fr[4][4];
#pragma unroll
            for (int t = 0; t < 4; t++) {
                int it = base + t;
                int aid = artist_ids[it], bid = album_ids[it];
                fr[t][0] = audio[it * 64 + lane];
                fr[t][1] = audio[it * 64 + 32 + lane];
                fr[t][2] = artist_w[aid * 64 + lane] + album_w[bid * 64 + lane];
                fr[t][3] = artist_w[aid * 64 + 32 + lane] + album_w[bid * 64 + 32 + lane];
            }
            float2 y[4];
#pragma unroll
            for (int t = 0; t < 4; t++) y[t] = bb;
#pragma unroll
            for (int j = 0; j < 4; j++) {
#pragma unroll
                for (int kk = 0; kk < 32; kk++) {
                    int k = j * 32 + kk;
                    float2 w2 = *(const float2*)&Wt[k * 64 + 2 * lane];
#pragma unroll
                    for (int t = 0; t < 4; t++) {
                        float fk = __shfl_sync(0xffffffffu, fr[t][j], kk);
                        y[t].x += fk * w2.x;
                        y[t].y += fk * w2.y;
                    }
                }
            }
#pragma unroll
            for (int t = 0; t < 4; t++) {
                float s = y[t].x * y[t].x + y[t].y * y[t].y;
#pragma unroll
                for (int o = 16; o; o >>= 1) s += __shfl_xor_sync(0xffffffffu, s, o);
                float inv = 1.0f / fmaxf(sqrtf(s), 1e-12f);
                int row = UU + base + t;
                g_xh0[row * 32 + lane] =
                    __floats2half2_rn(y[t].x * inv, y[t].y * inv);
            }
        }
    } else if (b < NB_ITEM + NB_DEG) {
        // ---- degree/count atomics + free edge ranks ----
        int e = (b - NB_ITEM) * 256 + tid;
        if (e >= EE) return;
        float w = fmaxf(ew[e], 1e-6f);
        unsigned long long pack = __float2ull_rn(w * FIX_SCALE) | (1ull << 40);
        int u = u_idx[e], iU = i_idx[e] + UU;
        unsigned long long ou = atomicAdd(&g_dc[u], pack);
        unsigned long long oi = atomicAdd(&g_dc[iU], pack);
        int ru = (int)(ou >> 40);
        int ri = (int)(oi >> 40);
        g_rank[e] = (ru & 0xffff) | (ri << 16);
    } else {
        // ---- user embeddings ----
        int w = (b - NB_ITEM - NB_DEG) * 8 + wid;
        if (w >= UU) return;
        float2 a = ((const float2*)user_w)[w * 32 + lane];
        float s = a.x * a.x + a.y * a.y;
#pragma unroll
        for (int o = 16; o; o >>= 1) s += __shfl_xor_sync(0xffffffffu, s, o);
        float inv = 1.0f / fmaxf(sqrtf(s), 1e-12f);
        g_xh0[w * 32 + lane] = __floats2half2_rn(a.x * inv, a.y * inv);
    }
}

// =============== scan1: shfl-based block scan (+dinv folded in) ===============
__global__ void k_scan1() {
    __shared__ int ws[32];
    int i = blockIdx.x * 1024 + threadIdx.x;
    int lane = threadIdx.x & 31, wid = threadIdx.x >> 5;
    int v = 0;
    if (i < NN) {
        unsigned long long dc = g_dc[i];
        float d = (float)(dc & DEG_MASK) * FIX_INV;
        g_dinv[i] = rsqrtf(d);          // d >= 1 always (self loop)
        v = (int)(dc >> 40);
    }
    int s = v;
#pragma unroll
    for (int o = 1; o < 32; o <<= 1) {
        int t = __shfl_up_sync(0xffffffffu, s, o);
        if (lane >= o) s += t;
    }
    if (lane == 31) ws[wid] = s;
    __syncthreads();
    if (wid == 0) {
        int w2 = ws[lane];
#pragma unroll
        for (int o = 1; o < 32; o <<= 1) {
            int t = __shfl_up_sync(0xffffffffu, w2, o);
            if (lane >= o) w2 += t;
        }
        ws[lane] = w2;
    }
    __syncthreads();
    int base = wid ? ws[wid - 1] : 0;
    int incl = base + s;
    if (i < NN) g_incl[i] = incl;
    if (threadIdx.x == 1023) g_bsum[blockIdx.x] = incl;  // block total
}

// =============== scan3: ptr + packed (excl ptr, dinv) for k_fill ===============
__global__ void k_scan3() {
    __shared__ int red[8];
    int tid = threadIdx.x;
    int lane = tid & 31, wid = tid >> 5;
    int c = blockIdx.x >> 2;             // scan1-chunk index for this block's nodes
    int acc = 0;
    for (int k = tid; k < c; k += 256) acc += g_bsum[k];
#pragma unroll
    for (int o = 16; o; o >>= 1) acc += __shfl_xor_sync(0xffffffffu, acc, o);
    if (lane == 0) red[wid] = acc;
    __syncthreads();
    int base = red[0] + red[1] + red[2] + red[3]
             + red[4] + red[5] + red[6] + red[7];
    int i = blockIdx.x * 256 + tid;
    if (i < NN) {
        int incl = g_incl[i] + base;
        g_ptr[i + 1] = incl;
        int cnt = (int)(g_dc[i] >> 40);          // sequential 8B load
        g_pd[i] = make_int2(incl - cnt, __float_as_int(g_dinv[i]));
    }
    if (i == 0) g_ptr[0] = 0;
}

// =============== CSR fill: one 8B random load per endpoint ===============
__global__ void k_fill(const float* __restrict__ ew,
                       const int* __restrict__ u_idx,
                       const int* __restrict__ i_idx) {
    int e = blockIdx.x * blockDim.x + threadIdx.x;
    if (e >= EE) return;
    int u = u_idx[e], iU = i_idx[e] + UU;
    int2 pu = g_pd[u];                  // (excl ptr, dinv) one line each
    int2 pi = g_pd[iU];
    float w = __int_as_float(pu.y) * fmaxf(ew[e], 1e-6f) * __int_as_float(pi.y);
    int wi = __float_as_int(w);
    int r = g_rank[e];
    g_csr[pu.x + (r & 0xffff)] = make_int2(iU, wi);
    g_csr[pi.x + (r >> 16)] = make_int2(u, wi);
}

// =============== gather core: exact R6 loop (frozen). Returns self row. ===============
// On return, a[] holds the full aggregated row including the self-loop term,
// and *self_out holds this node's own raw 16B chunk (for reuse by the caller).
__device__ __forceinline__ void gather8(const __half2* __restrict__ x, int n,
                                        int sub, int lane8, float* a,
                                        uint4* self_out) {
    int s = g_ptr[n], e = g_ptr[n + 1];
#pragma unroll 2
    for (int j = s; j < e; j += 4) {
        int jj = j + sub;
        int2 ent = (jj < e) ? g_csr[jj] : make_int2(n, 0);   // w=0 pad: no-op
        float w = __int_as_float(ent.y);
        uint4 xv = ((const uint4*)(x + ent.x * 32))[lane8];  // 16B of the 128B row
        float2 f0 = __half22float2(*(__half2*)&xv.x);
        float2 f1 = __half22float2(*(__half2*)&xv.y);
        float2 f2 = __half22float2(*(__half2*)&xv.z);
        float2 f3 = __half22float2(*(__half2*)&xv.w);
        a[0] += w * f0.x; a[1] += w * f0.y;
        a[2] += w * f1.x; a[3] += w * f1.y;
        a[4] += w * f2.x; a[5] += w * f2.y;
        a[6] += w * f3.x; a[7] += w * f3.y;
    }
#pragma unroll
    for (int i = 0; i < 8; i++) {
        a[i] += __shfl_xor_sync(0xffffffffu, a[i], 8);
        a[i] += __shfl_xor_sync(0xffffffffu, a[i], 16);
    }
    float sn = g_dinv[n]; sn *= sn;
    uint4 sv = ((const uint4*)(x + n * 32))[lane8];
    float2 s0 = __half22float2(*(__half2*)&sv.x);
    float2 s1 = __half22float2(*(__half2*)&sv.y);
    float2 s2 = __half22float2(*(__half2*)&sv.z);
    float2 s3 = __half22float2(*(__half2*)&sv.w);
    a[0] += sn * s0.x; a[1] += sn * s0.y;
    a[2] += sn * s1.x; a[3] += sn * s1.y;
    a[4] += sn * s2.x; a[5] += sn * s2.y;
    a[6] += sn * s3.x; a[7] += sn * s3.y;
    *self_out = sv;
}

// =============== middle propagation layer: stage-selected device globals ===============
__global__ void k_pull(int stage) {
    int n = (blockIdx.x * blockDim.x + threadIdx.x) >> 5;
    if (n >= NN) return;
    const __half2* __restrict__ x = stage ? g_xh1 : g_xh0;
    __half2* __restrict__ xout = stage ? g_xh2 : g_xh1;
    int lane = threadIdx.x & 31;
    int sub = lane >> 3, lane8 = lane & 7;
    float a[8] = {0, 0, 0, 0, 0, 0, 0, 0};
    uint4 sv;
    gather8(x, n, sub, lane8, a, &sv);
    if (sub == 0) {
        uint4 o;
        *(__half2*)&o.x = __floats2half2_rn(a[0], a[1]);
        *(__half2*)&o.y = __floats2half2_rn(a[2], a[3]);
        *(__half2*)&o.z = __floats2half2_rn(a[4], a[5]);
        *(__half2*)&o.w = __floats2half2_rn(a[6], a[7]);
        ((uint4*)(xout + n * 32))[lane8] = o;
    }
}

// =============== final layer: gather x3 + acc sum + l2norm -> out (fp32) ===============
__global__ void k_pull_final(float* __restrict__ out) {
    int n = (blockIdx.x * blockDim.x + threadIdx.x) >> 5;
    if (n >= NN) return;
    int lane = threadIdx.x & 31;
    int sub = lane >> 3, lane8 = lane & 7;
    float a[8] = {0, 0, 0, 0, 0, 0, 0, 0};
    uint4 h2;                            // own x2 row chunk (from gather's self load)
    gather8(g_xh2, n, sub, lane8, a, &h2);   // a = x3 (fp32, un-rounded)
    // add x0 + x1 + x2 own-row chunks (all half; x2 reused from gather)
    uint4 h0 = ((const uint4*)(g_xh0 + n * 32))[lane8];
    uint4 h1 = ((const uint4*)(g_xh1 + n * 32))[lane8];
    float2 d0 = __half22float2(*(__half2*)&h0.x);
    float2 d1 = __half22float2(*(__half2*)&h0.y);
    float2 d2 = __half22float2(*(__half2*)&h0.z);
    float2 d3 = __half22float2(*(__half2*)&h0.w);
    float2 b0 = __half22float2(*(__half2*)&h1.x), c0 = __half22float2(*(__half2*)&h2.x);
    float2 b1 = __half22float2(*(__half2*)&h1.y), c1 = __half22float2(*(__half2*)&h2.y);
    float2 b2 = __half22float2(*(__half2*)&h1.z), c2 = __half22float2(*(__half2*)&h2.z);
    float2 b3 = __half22float2(*(__half2*)&h1.w), c3 = __half22float2(*(__half2*)&h2.w);
    a[0] = (a[0] + d0.x + b0.x + c0.x) * 0.25f;
    a[1] = (a[1] + d0.y + b0.y + c0.y) * 0.25f;
    a[2] = (a[2] + d1.x + b1.x + c1.x) * 0.25f;
    a[3] = (a[3] + d1.y + b1.y + c1.y) * 0.25f;
    a[4] = (a[4] + d2.x + b2.x + c2.x) * 0.25f;
    a[5] = (a[5] + d2.y + b2.y + c2.y) * 0.25f;
    a[6] = (a[6] + d3.x + b3.x + c3.x) * 0.25f;
    a[7] = (a[7] + d3.y + b3.y + c3.y) * 0.25f;
    float s = 0.f;
#pragma unroll
    for (int i = 0; i < 8; i++) s += a[i] * a[i];
    s += __shfl_xor_sync(0xffffffffu, s, 1);
    s += __shfl_xor_sync(0xffffffffu, s, 2);
    s += __shfl_xor_sync(0xffffffffu, s, 4);
    float inv = 1.0f / fmaxf(sqrtf(s), 1e-12f);
    if (sub == 0) {
        float4 o0 = make_float4(a[0] * inv, a[1] * inv, a[2] * inv, a[3] * inv);
        float4 o1 = make_float4(a[4] * inv, a[5] * inv, a[6] * inv, a[7] * inv);
        ((float4*)(out + n * 64))[2 * lane8] = o0;
        ((float4*)(out + n * 64))[2 * lane8 + 1] = o1;
    }
}

extern "C" void kernel_launch(void* const* d_in, const int* in_sizes, int n_in,
                              void* d_out, int out_size) {
    const float* user_w     = (const float*)d_in[0];
    const float* item_audio = (const float*)d_in[1];
    const float* artist_w   = (const float*)d_in[2];
    const float* album_w    = (const float*)d_in[3];
    const float* proj_W     = (const float*)d_in[4];
    const float* proj_b     = (const float*)d_in[5];
    const float* edge_w     = (const float*)d_in[6];
    const int*   u_idx      = (const int*)d_in[7];
    const int*   i_idx      = (const int*)d_in[8];
    const int*   artist_ids = (const int*)d_in[9];
    const int*   album_ids  = (const int*)d_in[10];

    // init + fused (L0 embeddings || degree atomics)
    k_init<<<(NN / 2 + 255) / 256, 256>>>();
    k_main<<<NB_MAIN, 256>>>(user_w, item_audio, artist_w, album_w,
                             proj_W, proj_b, artist_ids, album_ids,
                             edge_w, u_idx, i_idx);

    // CSR offsets + fill
    k_scan1<<<NB1, 1024>>>();
    k_scan3<<<(NN + 255) / 256, 256>>>();
    k_fill<<<(EE + 255) / 256, 256>>>(edge_w, u_idx, i_idx);

    // 3 propagation layers; last one fuses acc-sum + final l2norm
    int nb = (NN * 32 + 255) / 256;
    k_pull<<<nb, 256>>>(0);
    k_pull<<<nb, 256>>>(1);
    k_pull_final<<<nb, 256>>>((float*)d_out);
}

// round 16
// speedup vs baseline: 1.0016x; 1.0016x over previous
#include <cuda_runtime.h>
#include <cuda_fp16.h>

#define UU 100000
#define II 50000
#define DD 64
#define EE 2000000
#define NN 150000           // UU + II
#define E2 4000000          // 2*EE
#define NB1 147             // ceil(NN/1024)

#define NB_ITEM 296
#define NB_DEG  7813        // ceil(EE/256)
#define NB_USER 12500       // 100000 warps / 8 per block
#define NB_MAIN (NB_ITEM + NB_DEG + NB_USER)

// ---- static scratch (allocation-free rule) ----
__device__ __half2 g_xh0[NN * 32];   // x0 (half; also the x0 term in the final sum)
__device__ __half2 g_xh1[NN * 32];   // x1
__device__ __half2 g_xh2[NN * 32];   // x2
__device__ float g_dinv[NN];
__device__ unsigned long long g_dc[NN];  // packed: deg fixed<40> | cnt<<40
__device__ int   g_rank[EE];       // per-edge (rank_u | rank_i<<16)
__device__ int   g_incl[NN];       // scan temp (inclusive in-block prefix)
__device__ int   g_ptr[NN + 1];    // CSR offsets
__device__ int2  g_pd[NN];         // (exclusive ptr, bitcast dinv) for k_fill
__device__ int   g_bsum[NB1];      // per-scan1-block totals
__device__ int2  g_csr[E2];        // (src_node, bitcast(norm_weight))

#define DEG_MASK ((1ull << 40) - 1ull)
#define FIX_SCALE 16777216.0f        // 2^24
#define FIX_INV   5.9604644775390625e-8f

// =============== tiny init: packed deg/cnt (self-loop w=1, cnt=0) ===============
__global__ void k_init() {
    int i = blockIdx.x * blockDim.x + threadIdx.x;   // pairs
    if (i * 2 < NN) {
        unsigned long long v = (unsigned long long)(1u << 24);
        ulonglong2* p = (ulonglong2*)g_dc;
        if (i * 2 + 1 < NN) p[i] = make_ulonglong2(v, v);
        else g_dc[i * 2] = v;
    }
}

// =============== fused main: item proj | degree atomics | user norm ===============
__global__ void k_main(const float* __restrict__ user_w,
                       const float* __restrict__ audio,
                       const float* __restrict__ artist_w,
                       const float* __restrict__ album_w,
                       const float* __restrict__ projW,
                       const float* __restrict__ projb,
                       const int* __restrict__ artist_ids,
                       const int* __restrict__ album_ids,
                       const float* __restrict__ ew,
                       const int* __restrict__ u_idx,
                       const int* __restrict__ i_idx) {
    __shared__ float Wt[128 * 64];   // 32 KB only: feat lives in registers
    int b = blockIdx.x;
    int tid = threadIdx.x;
    int wid = tid >> 5, lane = tid & 31;

    if (b < NB_ITEM) {
        // ---- item embeddings: feat in registers, shfl-broadcast GEMV ----
        for (int idx = tid; idx < 64 * 128; idx += 256) {
            int d = idx >> 7, k = idx & 127;
            Wt[k * 64 + d] = projW[idx];
        }
        __syncthreads();
        float2 bb = ((const float2*)projb)[lane];
        int gw = b * 8 + wid;
        int nw = NB_ITEM * 8;
        for (int g = gw; g < II / 4; g += nw) {
            int base = g * 4;
            float fr[4][4];
#pragma unroll
            for (int t = 0; t < 4; t++) {
                int it = base + t;
                int aid = artist_ids[it], bid = album_ids[it];
                fr[t][0] = audio[it * 64 + lane];
                fr[t][1] = audio[it * 64 + 32 + lane];
                fr[t][2] = artist_w[aid * 64 + lane] + album_w[bid * 64 + lane];
                fr[t][3] = artist_w[aid * 64 + 32 + lane] + album_w[bid * 64 + 32 + lane];
            }
            float2 y[4];
#pragma unroll
            for (int t = 0; t < 4; t++) y[t] = bb;
#pragma unroll
            for (int j = 0; j < 4; j++) {
#pragma unroll
                for (int kk = 0; kk < 32; kk++) {
                    int k = j * 32 + kk;
                    float2 w2 = *(const float2*)&Wt[k * 64 + 2 * lane];
#pragma unroll
                    for (int t = 0; t < 4; t++) {
                        float fk = __shfl_sync(0xffffffffu, fr[t][j], kk);
                        y[t].x += fk * w2.x;
                        y[t].y += fk * w2.y;
                    }
                }
            }
#pragma unroll
            for (int t = 0; t < 4; t++) {
                float s = y[t].x * y[t].x + y[t].y * y[t].y;
#pragma unroll
                for (int o = 16; o; o >>= 1) s += __shfl_xor_sync(0xffffffffu, s, o);
                float inv = 1.0f / fmaxf(sqrtf(s), 1e-12f);
                int row = UU + base + t;
                g_xh0[row * 32 + lane] =
                    __floats2half2_rn(y[t].x * inv, y[t].y * inv);
            }
        }
    } else if (b < NB_ITEM + NB_DEG) {
        // ---- degree/count atomics + free edge ranks ----
        int e = (b - NB_ITEM) * 256 + tid;
        if (e >= EE) return;
        float w = fmaxf(ew[e], 1e-6f);
        unsigned long long pack = __float2ull_rn(w * FIX_SCALE) | (1ull << 40);
        int u = u_idx[e], iU = i_idx[e] + UU;
        unsigned long long ou = atomicAdd(&g_dc[u], pack);
        unsigned long long oi = atomicAdd(&g_dc[iU], pack);
        int ru = (int)(ou >> 40);
        int ri = (int)(oi >> 40);
        g_rank[e] = (ru & 0xffff) | (ri << 16);
    } else {
        // ---- user embeddings ----
        int w = (b - NB_ITEM - NB_DEG) * 8 + wid;
        if (w >= UU) return;
        float2 a = ((const float2*)user_w)[w * 32 + lane];
        float s = a.x * a.x + a.y * a.y;
#pragma unroll
        for (int o = 16; o; o >>= 1) s += __shfl_xor_sync(0xffffffffu, s, o);
        float inv = 1.0f / fmaxf(sqrtf(s), 1e-12f);
        g_xh0[w * 32 + lane] = __floats2half2_rn(a.x * inv, a.y * inv);
    }
}

// =============== scan1: shfl-based block scan (+dinv folded in) ===============
__global__ void k_scan1() {
    __shared__ int ws[32];
    int i = blockIdx.x * 1024 + threadIdx.x;
    int lane = threadIdx.x & 31, wid = threadIdx.x >> 5;
    int v = 0;
    if (i < NN) {
        unsigned long long dc = g_dc[i];
        float d = (float)(dc & DEG_MASK) * FIX_INV;
        g_dinv[i] = rsqrtf(d);          // d >= 1 always (self loop)
        v = (int)(dc >> 40);
    }
    int s = v;
#pragma unroll
    for (int o = 1; o < 32; o <<= 1) {
        int t = __shfl_up_sync(0xffffffffu, s, o);
        if (lane >= o) s += t;
    }
    if (lane == 31) ws[wid] = s;
    __syncthreads();
    if (wid == 0) {
        int w2 = ws[lane];
#pragma unroll
        for (int o = 1; o < 32; o <<= 1) {
            int t = __shfl_up_sync(0xffffffffu, w2, o);
            if (lane >= o) w2 += t;
        }
        ws[lane] = w2;
    }
    __syncthreads();
    int base = wid ? ws[wid - 1] : 0;
    int incl = base + s;
    if (i < NN) g_incl[i] = incl;
    if (threadIdx.x == 1023) g_bsum[blockIdx.x] = incl;  // block total
}

// =============== scan3: ptr + packed (excl ptr, dinv) for k_fill ===============
__global__ void k_scan3() {
    __shared__ int red[8];
    int tid = threadIdx.x;
    int lane = tid & 31, wid = tid >> 5;
    int c = blockIdx.x >> 2;             // scan1-chunk index for this block's nodes
    int acc = 0;
    for (int k = tid; k < c; k += 256) acc += g_bsum[k];
#pragma unroll
    for (int o = 16; o; o >>= 1) acc += __shfl_xor_sync(0xffffffffu, acc, o);
    if (lane == 0) red[wid] = acc;
    __syncthreads();
    int base = red[0] + red[1] + red[2] + red[3]
             + red[4] + red[5] + red[6] + red[7];
    int i = blockIdx.x * 256 + tid;
    if (i < NN) {
        int incl = g_incl[i] + base;
        g_ptr[i + 1] = incl;
        int cnt = (int)(g_dc[i] >> 40);          // sequential 8B load
        g_pd[i] = make_int2(incl - cnt, __float_as_int(g_dinv[i]));
    }
    if (i == 0) g_ptr[0] = 0;
}

// =============== CSR fill: one 8B random load per endpoint ===============
__global__ void k_fill(const float* __restrict__ ew,
                       const int* __restrict__ u_idx,
                       const int* __restrict__ i_idx) {
    int e = blockIdx.x * blockDim.x + threadIdx.x;
    if (e >= EE) return;
    int u = u_idx[e], iU = i_idx[e] + UU;
    int2 pu = g_pd[u];                  // (excl ptr, dinv) one line each
    int2 pi = g_pd[iU];
    float w = __int_as_float(pu.y) * fmaxf(ew[e], 1e-6f) * __int_as_float(pi.y);
    int wi = __float_as_int(w);
    int r = g_rank[e];
    g_csr[pu.x + (r & 0xffff)] = make_int2(iU, wi);
    g_csr[pi.x + (r >> 16)] = make_int2(u, wi);
}

// =============== gather core: exact R6 shape (proven fastest; frozen) ===============
__device__ __forceinline__ void gather8(const __half2* __restrict__ x, int n,
                                        int sub, int lane8, float* a) {
    int s = g_ptr[n], e = g_ptr[n + 1];
#pragma unroll 2
    for (int j = s; j < e; j += 4) {
        int jj = j + sub;
        int2 ent = (jj < e) ? g_csr[jj] : make_int2(n, 0);   // w=0 pad: no-op
        float w = __int_as_float(ent.y);
        uint4 xv = ((const uint4*)(x + ent.x * 32))[lane8];  // 16B of the 128B row
        float2 f0 = __half22float2(*(__half2*)&xv.x);
        float2 f1 = __half22float2(*(__half2*)&xv.y);
        float2 f2 = __half22float2(*(__half2*)&xv.z);
        float2 f3 = __half22float2(*(__half2*)&xv.w);
        a[0] += w * f0.x; a[1] += w * f0.y;
        a[2] += w * f1.x; a[3] += w * f1.y;
        a[4] += w * f2.x; a[5] += w * f2.y;
        a[6] += w * f3.x; a[7] += w * f3.y;
    }
#pragma unroll
    for (int i = 0; i < 8; i++) {
        a[i] += __shfl_xor_sync(0xffffffffu, a[i], 8);
        a[i] += __shfl_xor_sync(0xffffffffu, a[i], 16);
    }
    float sn = g_dinv[n]; sn *= sn;
    uint4 sv = ((const uint4*)(x + n * 32))[lane8];
    float2 s0 = __half22float2(*(__half2*)&sv.x);
    float2 s1 = __half22float2(*(__half2*)&sv.y);
    float2 s2 = __half22float2(*(__half2*)&sv.z);
    float2 s3 = __half22float2(*(__half2*)&sv.w);
    a[0] += sn * s0.x; a[1] += sn * s0.y;
    a[2] += sn * s1.x; a[3] += sn * s1.y;
    a[4] += sn * s2.x; a[5] += sn * s2.y;
    a[6] += sn * s3.x; a[7] += sn * s3.y;
}

// =============== middle propagation layer: stage-selected device globals ===============
__global__ void k_pull(int stage) {
    int n = (blockIdx.x * blockDim.x + threadIdx.x) >> 5;
    if (n >= NN) return;
    const __half2* __restrict__ x = stage ? g_xh1 : g_xh0;
    __half2* __restrict__ xout = stage ? g_xh2 : g_xh1;
    int lane = threadIdx.x & 31;
    int sub = lane >> 3, lane8 = lane & 7;
    float a[8] = {0, 0, 0, 0, 0, 0, 0, 0};
    gather8(x, n, sub, lane8, a);
    if (sub == 0) {
        uint4 o;
        *(__half2*)&o.x = __floats2half2_rn(a[0], a[1]);
        *(__half2*)&o.y = __floats2half2_rn(a[2], a[3]);
        *(__half2*)&o.z = __floats2half2_rn(a[4], a[5]);
        *(__half2*)&o.w = __floats2half2_rn(a[6], a[7]);
        ((uint4*)(xout + n * 32))[lane8] = o;
    }
}

// =============== final layer: gather x3 + acc sum + l2norm -> out (fp32) ===============
__global__ void k_pull_final(float* __restrict__ out) {
    int n = (blockIdx.x * blockDim.x + threadIdx.x) >> 5;
    if (n >= NN) return;
    int lane = threadIdx.x & 31;
    int sub = lane >> 3, lane8 = lane & 7;
    float a[8] = {0, 0, 0, 0, 0, 0, 0, 0};
    gather8(g_xh2, n, sub, lane8, a);   // a = x3 (fp32, un-rounded)
    // add x0 + x1 + x2 own-row chunks (all half)
    uint4 h0 = ((const uint4*)(g_xh0 + n * 32))[lane8];
    uint4 h1 = ((const uint4*)(g_xh1 + n * 32))[lane8];
    uint4 h2 = ((const uint4*)(g_xh2 + n * 32))[lane8];
    float2 d0 = __half22float2(*(__half2*)&h0.x);
    float2 d1 = __half22float2(*(__half2*)&h0.y);
    float2 d2 = __half22float2(*(__half2*)&h0.z);
    float2 d3 = __half22float2(*(__half2*)&h0.w);
    float2 b0 = __half22float2(*(__half2*)&h1.x), c0 = __half22float2(*(__half2*)&h2.x);
    float2 b1 = __half22float2(*(__half2*)&h1.y), c1 = __half22float2(*(__half2*)&h2.y);
    float2 b2 = __half22float2(*(__half2*)&h1.z), c2 = __half22float2(*(__half2*)&h2.z);
    float2 b3 = __half22float2(*(__half2*)&h1.w), c3 = __half22float2(*(__half2*)&h2.w);
    a[0] = (a[0] + d0.x + b0.x + c0.x) * 0.25f;
    a[1] = (a[1] + d0.y + b0.y + c0.y) * 0.25f;
    a[2] = (a[2] + d1.x + b1.x + c1.x) * 0.25f;
    a[3] = (a[3] + d1.y + b1.y + c1.y) * 0.25f;
    a[4] = (a[4] + d2.x + b2.x + c2.x) * 0.25f;
    a[5] = (a[5] + d2.y + b2.y + c2.y) * 0.25f;
    a[6] = (a[6] + d3.x + b3.x + c3.x) * 0.25f;
    a[7] = (a[7] + d3.y + b3.y + c3.y) * 0.25f;
    float s = 0.f;
#pragma unroll
    for (int i = 0; i < 8; i++) s += a[i] * a[i];
    s += __shfl_xor_sync(0xffffffffu, s, 1);
    s += __shfl_xor_sync(0xffffffffu, s, 2);
    s += __shfl_xor_sync(0xffffffffu, s, 4);
    float inv = 1.0f / fmaxf(sqrtf(s), 1e-12f);
    if (sub == 0) {
        float4 o0 = make_float4(a[0] * inv, a[1] * inv, a[2] * inv, a[3] * inv);
        float4 o1 = make_float4(a[4] * inv, a[5] * inv, a[6] * inv, a[7] * inv);
        ((float4*)(out + n * 64))[2 * lane8] = o0;
        ((float4*)(out + n * 64))[2 * lane8 + 1] = o1;
    }
}

extern "C" void kernel_launch(void* const* d_in, const int* in_sizes, int n_in,
                              void* d_out, int out_size) {
    const float* user_w     = (const float*)d_in[0];
    const float* item_audio = (const float*)d_in[1];
    const float* artist_w   = (const float*)d_in[2];
    const float* album_w    = (const float*)d_in[3];
    const float* proj_W     = (const float*)d_in[4];
    const float* proj_b     = (const float*)d_in[5];
    const float* edge_w     = (const float*)d_in[6];
    const int*   u_idx      = (const int*)d_in[7];
    const int*   i_idx      = (const int*)d_in[8];
    const int*   artist_ids = (const int*)d_in[9];
    const int*   album_ids  = (const int*)d_in[10];

    // init + fused (L0 embeddings || degree atomics)
    k_init<<<(NN / 2 + 255) / 256, 256>>>();
    k_main<<<NB_MAIN, 256>>>(user_w, item_audio, artist_w, album_w,
                             proj_W, proj_b, artist_ids, album_ids,
                             edge_w, u_idx, i_idx);

    // CSR offsets + fill
    k_scan1<<<NB1, 1024>>>();
    k_scan3<<<(NN + 255) / 256, 256>>>();
    k_fill<<<(EE + 255) / 256, 256>>>(edge_w, u_idx, i_idx);

    // 3 propagation layers; last one fuses acc-sum + final l2norm
    int nb = (NN * 32 + 255) / 256;
    k_pull<<<nb, 256>>>(0);
    k_pull<<<nb, 256>>>(1);
    k_pull_final<<<nb, 256>>>((float*)d_out);
}